// round 6
// baseline (speedup 1.0000x reference)
#include <cuda_runtime.h>
#include <cuda_bf16.h>
#include <math.h>

// ---------------------------------------------------------------------------
// AsymmetricLossCustomPriorityRankNewNegOne  (B=4096, C=9605, L=20)
// Warp-per-row. Two batched memory epochs per row:
//   epoch 1: all y loads in flight (MLP=8/lane) -> ordered first-positive
//   epoch 2: wl row   -> read ~gs floats of the priority group
//            other row-> all x & y_neg loads in flight (MLP=16/lane)
// Fast path is device-verified; generic slow path kept.
// ---------------------------------------------------------------------------

#define MAXC 16384
#define JINF 0x7fffffff

__device__ unsigned            g_bits[MAXC];
__device__ unsigned long long  g_pack[MAXC];   // (bits<<32 | c)  [slow path]
__device__ int                 g_ucount;
__device__ int                 g_cmin;
__device__ int                 g_cmax;
__device__ int                 g_notfast;
__device__ int                 g_gs;           // uniform group size candidate
__device__ int                 g_is_u8;

__device__ __forceinline__ unsigned enc_f(float f) {
    unsigned u = __float_as_uint(f);
    return (u & 0x80000000u) ? ~u : (u | 0x80000000u);
}
__device__ __forceinline__ float dec_f(unsigned u) {
    return __uint_as_float((u & 0x80000000u) ? (u & 0x7fffffffu) : ~u);
}
__device__ __forceinline__ float sigmoidf_(float x) {
    return 1.0f / (1.0f + expf(-x));
}
// d = x2 - x1 + 0.05; s = sigmoid(10 d); d>0 -> 2s else s
__device__ __forceinline__ float rank_loss_(float x1, float x2) {
    float d = x2 - x1 + 0.05f;
    float s = sigmoidf_(10.0f * d);
    return (d > 0.0f) ? 2.0f * s : s;
}

// --- kernel 1: init + parallel width detect ----------------------------------
__global__ void init_kernel(float* out, int out_size,
                            const unsigned int* wl_as_u32, int n_probe) {
    __shared__ int flag;
    int t = threadIdx.x;
    if (t == 0) flag = 0;
    __syncthreads();
    for (int i = t; i < out_size; i += blockDim.x) out[i] = 0.0f;
    if (t < n_probe && wl_as_u32[t] > 1u) flag = 1;
    __syncthreads();
    if (t == 0) {
        g_is_u8   = flag;
        g_ucount  = 0;
        g_cmin    = 0x7fffffff;
        g_cmax    = -1;
        g_notfast = 0;
        g_gs      = 0;
    }
}

// --- kernel 2: per-class group bitmask + stats ---------------------------------
__global__ void build_bits_kernel(const void* wl, int C, int L) {
    __shared__ int bmin, bmax, bbad, bgs;
    if (threadIdx.x == 0) { bmin = 0x7fffffff; bmax = -1; bbad = 0; bgs = 0; }
    __syncthreads();

    int c = blockIdx.x * blockDim.x + threadIdx.x;
    unsigned b = 0;
    if (c < C) {
        if (g_is_u8) {
            const unsigned char* m = (const unsigned char*)wl;
            #pragma unroll 4
            for (int l = 0; l < L; l++)
                if (m[(size_t)l * C + c]) b |= (1u << l);
        } else {
            const int* m = (const int*)wl;
            #pragma unroll 4
            for (int l = 0; l < L; l++)
                if (m[(size_t)l * C + c]) b |= (1u << l);
        }
        g_bits[c] = b;
        if (b) {
            atomicMin(&bmin, c);
            atomicMax(&bmax, c);
            if (__popc(b) > 1) bbad = 1;
            if (b == 1u) atomicAdd(&bgs, 1);
        }
    }
    __syncthreads();
    if (threadIdx.x == 0) {
        if (bmax >= 0) { atomicMin(&g_cmin, bmin); atomicMax(&g_cmax, bmax); }
        if (bbad) g_notfast = 1;
        if (bgs)  atomicAdd(&g_gs, bgs);
    }
}

// --- kernel 3: compaction + exact fast-path verification -----------------------
__global__ void compact_kernel(int C) {
    __shared__ int woff[8];
    __shared__ int sbase;
    int c    = blockIdx.x * 256 + threadIdx.x;
    int lane = threadIdx.x & 31;
    int wid  = threadIdx.x >> 5;

    unsigned b = (c < C) ? g_bits[c] : 0u;
    unsigned ballot = __ballot_sync(0xffffffffu, b != 0u);
    if (lane == 0) woff[wid] = __popc(ballot);
    __syncthreads();
    if (threadIdx.x == 0) {
        int acc = 0;
        #pragma unroll
        for (int w = 0; w < 8; w++) { int t = woff[w]; woff[w] = acc; acc += t; }
        sbase = atomicAdd(&g_ucount, acc);
    }
    __syncthreads();
    if (b) {
        int pos = sbase + woff[wid] + __popc(ballot & ((1u << lane) - 1u));
        g_pack[pos] = ((unsigned long long)b << 32) | (unsigned)c;

        int gs = g_gs;
        if (gs > 0) {
            unsigned M = (4194304u + (unsigned)gs - 1u) / (unsigned)gs;
            unsigned j = (unsigned)(c - g_cmin);
            unsigned gm = (j * M) >> 22;
            if ((int)gm != (__ffs(b) - 1) || gm >= 32u) g_notfast = 1;
        } else {
            g_notfast = 1;
        }
    }
}

// --- kernel 4: warp-per-row loss, 2-epoch batched ---------------------------------
__global__ __launch_bounds__(256)
void row_loss_kernel(const float* __restrict__ x,
                     const int*   __restrict__ y,
                     const int*   __restrict__ yneg,
                     int C, int B, float* __restrict__ out) {
    __shared__ float sSum;
    __shared__ unsigned sG[8][32];           // slow path per-warp group maxes

    const int lane = threadIdx.x & 31;
    const int wid  = threadIdx.x >> 5;
    const int row  = blockIdx.x * 8 + wid;

    if (threadIdx.x == 0) sSum = 0.0f;
    __syncthreads();

    const int n    = g_ucount;
    const int cmin = g_cmin;
    const bool fast = (!g_notfast) && (g_cmax - cmin + 1 == n);

    float warp_loss = 0.0f;

    if (row < B && fast) {
        const int gs = g_gs;
        const unsigned M = (4194304u + (unsigned)gs - 1u) / (unsigned)gs;
        const long long base = (long long)row * C + cmin;
        const float* __restrict__ xr  = x    + base;
        const int*   __restrict__ yr  = y    + base;
        const int*   __restrict__ ynr = yneg + base;

        int p = (int)((4 - (base & 3)) & 3);
        if (p > n) p = n;
        const int nv = (n - p) >> 2;          // vec4 chunks
        const int ts = p + 4 * nv;
        const int ntail = n - ts;

        // ================= epoch 1: y only, all loads batched ==============
        int jmin = JINF;
        {
            int ypeel = (lane < p)     ? __ldg(yr + lane)    : 0;
            int ytail = (lane < ntail) ? __ldg(yr + ts + lane) : 0;

            for (int b0 = 0; b0 < nv; b0 += 256) {
                int4 yv[8];
                #pragma unroll
                for (int k = 0; k < 8; k++) {
                    const int i = b0 + lane + k * 32;
                    yv[k] = (i < nv) ? *(const int4*)(yr + p + 4 * i)
                                     : make_int4(0, 0, 0, 0);
                }
                #pragma unroll
                for (int k = 0; k < 8; k++) {
                    const int i = b0 + lane + k * 32;
                    if (i < nv && jmin == JINF) {
                        const int j0 = p + 4 * i;
                        if      (yv[k].x) jmin = j0;
                        else if (yv[k].y) jmin = j0 + 1;
                        else if (yv[k].z) jmin = j0 + 2;
                        else if (yv[k].w) jmin = j0 + 3;
                    }
                }
                if (__any_sync(0xffffffffu, jmin != JINF)) break;
            }
            if (ypeel && lane < jmin) jmin = lane;          // peel j == lane < p
            if (ytail && jmin == JINF) jmin = ts + lane;    // tail after all vec j
            #pragma unroll
            for (int off = 16; off > 0; off >>= 1)
                jmin = min(jmin, __shfl_xor_sync(0xffffffffu, jmin, off));
        }

        if (jmin != JINF) {
            // ============ epoch 2a: priority group's x (gs floats) =========
            const int fl = (int)(((unsigned)jmin * M) >> 22);
            const int j0 = fl * gs;
            float m = -1e30f;
            for (int t = lane; t < gs; t += 32) {
                const int j = j0 + t;
                if (j < n) m = fmaxf(m, __ldg(xr + j));
            }
            #pragma unroll
            for (int off = 16; off > 0; off >>= 1)
                m = fmaxf(m, __shfl_xor_sync(0xffffffffu, m, off));
            warp_loss = rank_loss_(sigmoidf_(m), 0.5f);
        } else {
            // ============ epoch 2b: x & y_neg, all loads batched ============
            float mN = -1e30f, mW = -1e30f;
            {
                if (lane < p) {
                    const float xv = __ldg(xr + lane);
                    mN = fmaxf(mN, xv);
                    if (__ldg(ynr + lane)) mW = fmaxf(mW, xv);
                }
                if (lane < ntail) {
                    const int j = ts + lane;
                    const float xv = __ldg(xr + j);
                    mN = fmaxf(mN, xv);
                    if (__ldg(ynr + j)) mW = fmaxf(mW, xv);
                }
                for (int b0 = 0; b0 < nv; b0 += 256) {
                    float4 xv[8];
                    int4   nvv[8];
                    #pragma unroll
                    for (int k = 0; k < 8; k++) {
                        const int i = b0 + lane + k * 32;
                        if (i < nv) {
                            const int j0 = p + 4 * i;
                            xv[k]  = *(const float4*)(xr  + j0);
                            nvv[k] = *(const int4*)  (ynr + j0);
                        } else {
                            xv[k]  = make_float4(-1e30f, -1e30f, -1e30f, -1e30f);
                            nvv[k] = make_int4(0, 0, 0, 0);
                        }
                    }
                    #pragma unroll
                    for (int k = 0; k < 8; k++) {
                        mN = fmaxf(mN, fmaxf(fmaxf(xv[k].x, xv[k].y),
                                             fmaxf(xv[k].z, xv[k].w)));
                        if (nvv[k].x) mW = fmaxf(mW, xv[k].x);
                        if (nvv[k].y) mW = fmaxf(mW, xv[k].y);
                        if (nvv[k].z) mW = fmaxf(mW, xv[k].z);
                        if (nvv[k].w) mW = fmaxf(mW, xv[k].w);
                    }
                }
            }
            #pragma unroll
            for (int off = 16; off > 0; off >>= 1) {
                mN = fmaxf(mN, __shfl_xor_sync(0xffffffffu, mN, off));
                mW = fmaxf(mW, __shfl_xor_sync(0xffffffffu, mW, off));
            }
            warp_loss = 0.5f * rank_loss_(0.5f, sigmoidf_(mN))
                      + 0.5f * rank_loss_(0.5f, sigmoidf_(mW));
        }
    } else if (row < B) {
        // ---------------- generic slow path (warp-per-row) ----------------
        const unsigned KNEG = enc_f(-1e30f);
        sG[wid][lane] = KNEG;
        __syncwarp();

        unsigned locNon = KNEG, locWrong = KNEG, locPres = 0u;
        for (int i = lane; i < n; i += 32) {
            const unsigned long long pk = g_pack[i];
            const int c         = (int)(pk & 0xffffffffull);
            const unsigned bits = (unsigned)(pk >> 32);
            const long long o = (long long)row * C + c;
            const float xv = __ldg(x + o);
            const unsigned key = enc_f(xv);
            locNon = max(locNon, key);
            if (__ldg(yneg + o) != 0) locWrong = max(locWrong, key);
            if (__ldg(y    + o) != 0) locPres |= bits;
            unsigned bb = bits;
            while (bb) {
                const int l = __ffs(bb) - 1;
                bb &= bb - 1u;
                atomicMax(&sG[wid][l], key);
            }
        }
        #pragma unroll
        for (int off = 16; off > 0; off >>= 1) {
            locNon   = max(locNon,   __shfl_xor_sync(0xffffffffu, locNon,   off));
            locWrong = max(locWrong, __shfl_xor_sync(0xffffffffu, locWrong, off));
            locPres |= __shfl_xor_sync(0xffffffffu, locPres, off);
        }
        __syncwarp();
        if (lane == 0) {
            if (locPres) {
                const int fl = __ffs(locPres) - 1;
                warp_loss = rank_loss_(sigmoidf_(dec_f(sG[wid][fl])), 0.5f);
            } else {
                warp_loss = 0.5f * rank_loss_(0.5f, sigmoidf_(dec_f(locNon)))
                          + 0.5f * rank_loss_(0.5f, sigmoidf_(dec_f(locWrong)));
            }
        }
    }

    if (lane == 0 && row < B) atomicAdd(&sSum, warp_loss);
    __syncthreads();
    if (threadIdx.x == 0) atomicAdd(out, sSum);
}

// ---------------------------------------------------------------------------
extern "C" void kernel_launch(void* const* d_in, const int* in_sizes, int n_in,
                              void* d_out, int out_size) {
    const float* x    = (const float*)d_in[0];
    const int*   y    = (const int*)d_in[1];
    const int*   yneg = (const int*)d_in[2];
    const void*  wl   = d_in[3];

    const int C = 9605;
    const int L = in_sizes[3] / C;            // 20
    const int B = in_sizes[0] / C;            // 4096

    float* out = (float*)d_out;

    init_kernel<<<1, 256>>>(out, out_size, (const unsigned int*)wl, 256);
    build_bits_kernel<<<(C + 255) / 256, 256>>>(wl, C, L);
    compact_kernel<<<(C + 255) / 256, 256>>>(C);
    row_loss_kernel<<<(B + 7) / 8, 256>>>(x, y, yneg, C, B, out);
}

// round 7
// speedup vs baseline: 1.0019x; 1.0019x over previous
#include <cuda_runtime.h>
#include <cuda_bf16.h>
#include <math.h>

// ---------------------------------------------------------------------------
// AsymmetricLossCustomPriorityRankNewNegOne  (B=4096, C=9605, L=20)
// Warp-per-row, two batched memory epochs, REAL register-resident batching
// (launch_bounds(256,2) -> 128-reg ceiling), branchless consume, strided row
// mapping for wave balance. Fast path device-verified; slow path kept.
// ---------------------------------------------------------------------------

#define MAXC 16384
#define JINF 0x7fffffff

__device__ unsigned            g_bits[MAXC];
__device__ unsigned long long  g_pack[MAXC];   // (bits<<32 | c)  [slow path]
__device__ int                 g_ucount;
__device__ int                 g_cmin;
__device__ int                 g_cmax;
__device__ int                 g_notfast;
__device__ int                 g_gs;           // uniform group size candidate
__device__ int                 g_is_u8;

__device__ __forceinline__ unsigned enc_f(float f) {
    unsigned u = __float_as_uint(f);
    return (u & 0x80000000u) ? ~u : (u | 0x80000000u);
}
__device__ __forceinline__ float dec_f(unsigned u) {
    return __uint_as_float((u & 0x80000000u) ? (u & 0x7fffffffu) : ~u);
}
__device__ __forceinline__ float sigmoidf_(float x) {
    return 1.0f / (1.0f + expf(-x));
}
// d = x2 - x1 + 0.05; s = sigmoid(10 d); d>0 -> 2s else s
__device__ __forceinline__ float rank_loss_(float x1, float x2) {
    float d = x2 - x1 + 0.05f;
    float s = sigmoidf_(10.0f * d);
    return (d > 0.0f) ? 2.0f * s : s;
}

// --- kernel 1: init + parallel width detect ----------------------------------
__global__ void init_kernel(float* out, int out_size,
                            const unsigned int* wl_as_u32, int n_probe) {
    __shared__ int flag;
    int t = threadIdx.x;
    if (t == 0) flag = 0;
    __syncthreads();
    for (int i = t; i < out_size; i += blockDim.x) out[i] = 0.0f;
    if (t < n_probe && wl_as_u32[t] > 1u) flag = 1;
    __syncthreads();
    if (t == 0) {
        g_is_u8   = flag;
        g_ucount  = 0;
        g_cmin    = 0x7fffffff;
        g_cmax    = -1;
        g_notfast = 0;
        g_gs      = 0;
    }
}

// --- kernel 2: per-class group bitmask + stats ---------------------------------
__global__ void build_bits_kernel(const void* wl, int C, int L) {
    __shared__ int bmin, bmax, bbad, bgs;
    if (threadIdx.x == 0) { bmin = 0x7fffffff; bmax = -1; bbad = 0; bgs = 0; }
    __syncthreads();

    int c = blockIdx.x * blockDim.x + threadIdx.x;
    unsigned b = 0;
    if (c < C) {
        if (g_is_u8) {
            const unsigned char* m = (const unsigned char*)wl;
            #pragma unroll 4
            for (int l = 0; l < L; l++)
                if (m[(size_t)l * C + c]) b |= (1u << l);
        } else {
            const int* m = (const int*)wl;
            #pragma unroll 4
            for (int l = 0; l < L; l++)
                if (m[(size_t)l * C + c]) b |= (1u << l);
        }
        g_bits[c] = b;
        if (b) {
            atomicMin(&bmin, c);
            atomicMax(&bmax, c);
            if (__popc(b) > 1) bbad = 1;
            if (b == 1u) atomicAdd(&bgs, 1);
        }
    }
    __syncthreads();
    if (threadIdx.x == 0) {
        if (bmax >= 0) { atomicMin(&g_cmin, bmin); atomicMax(&g_cmax, bmax); }
        if (bbad) g_notfast = 1;
        if (bgs)  atomicAdd(&g_gs, bgs);
    }
}

// --- kernel 3: compaction + exact fast-path verification -----------------------
__global__ void compact_kernel(int C) {
    __shared__ int woff[8];
    __shared__ int sbase;
    int c    = blockIdx.x * 256 + threadIdx.x;
    int lane = threadIdx.x & 31;
    int wid  = threadIdx.x >> 5;

    unsigned b = (c < C) ? g_bits[c] : 0u;
    unsigned ballot = __ballot_sync(0xffffffffu, b != 0u);
    if (lane == 0) woff[wid] = __popc(ballot);
    __syncthreads();
    if (threadIdx.x == 0) {
        int acc = 0;
        #pragma unroll
        for (int w = 0; w < 8; w++) { int t = woff[w]; woff[w] = acc; acc += t; }
        sbase = atomicAdd(&g_ucount, acc);
    }
    __syncthreads();
    if (b) {
        int pos = sbase + woff[wid] + __popc(ballot & ((1u << lane) - 1u));
        g_pack[pos] = ((unsigned long long)b << 32) | (unsigned)c;

        int gs = g_gs;
        if (gs > 0) {
            unsigned M = (4194304u + (unsigned)gs - 1u) / (unsigned)gs;
            unsigned j = (unsigned)(c - g_cmin);
            unsigned gm = (j * M) >> 22;
            if ((int)gm != (__ffs(b) - 1) || gm >= 32u) g_notfast = 1;
        } else {
            g_notfast = 1;
        }
    }
}

// --- kernel 4: warp-per-row loss, register-resident batched --------------------
__global__ __launch_bounds__(256, 2)
void row_loss_kernel(const float* __restrict__ x,
                     const int*   __restrict__ y,
                     const int*   __restrict__ yneg,
                     int C, int B, float* __restrict__ out) {
    __shared__ float sSum;
    __shared__ unsigned sG[8][32];           // slow path per-warp group maxes

    const int lane = threadIdx.x & 31;
    const int wid  = threadIdx.x >> 5;
    // strided mapping: each block gets rows spread across the whole batch
    const int row  = wid * gridDim.x + blockIdx.x;

    if (threadIdx.x == 0) sSum = 0.0f;
    __syncthreads();

    const int n    = g_ucount;
    const int cmin = g_cmin;
    const bool fast = (!g_notfast) && (g_cmax - cmin + 1 == n);

    float warp_loss = 0.0f;

    if (row < B && fast) {
        const int gs = g_gs;
        const unsigned M = (4194304u + (unsigned)gs - 1u) / (unsigned)gs;
        const long long base = (long long)row * C + cmin;
        const float* __restrict__ xr  = x    + base;
        const int*   __restrict__ yr  = y    + base;
        const int*   __restrict__ ynr = yneg + base;

        int p = (int)((4 - (base & 3)) & 3);
        if (p > n) p = n;
        const int nv = (n - p) >> 2;          // vec4 chunks
        const int ts = p + 4 * nv;
        const int ntail = n - ts;

        // ================= epoch 1: y only, 8 int4 loads in flight ==========
        int jmin = JINF;
        {
            const int ypeel = (lane < p)     ? __ldg(yr + lane)      : 0;
            const int ytail = (lane < ntail) ? __ldg(yr + ts + lane) : 0;

            for (int b0 = 0; b0 < nv; b0 += 256) {
                int4 yv[8];
                #pragma unroll
                for (int k = 0; k < 8; k++) {
                    const int i = b0 + lane + k * 32;
                    yv[k] = (i < nv) ? __ldg((const int4*)(yr + p + 4 * i))
                                     : make_int4(0, 0, 0, 0);
                }
                #pragma unroll
                for (int k = 0; k < 8; k++) {
                    const int i = b0 + lane + k * 32;
                    if ((yv[k].x | yv[k].y | yv[k].z | yv[k].w) &&
                        i < nv && jmin == JINF) {
                        const int j0 = p + 4 * i;
                        if      (yv[k].x) jmin = j0;
                        else if (yv[k].y) jmin = j0 + 1;
                        else if (yv[k].z) jmin = j0 + 2;
                        else              jmin = j0 + 3;
                    }
                }
                if (__any_sync(0xffffffffu, jmin != JINF)) break;
            }
            if (ypeel && lane < jmin) jmin = lane;
            if (ytail && jmin == JINF) jmin = ts + lane;
            #pragma unroll
            for (int off = 16; off > 0; off >>= 1)
                jmin = min(jmin, __shfl_xor_sync(0xffffffffu, jmin, off));
        }

        if (jmin != JINF) {
            // ============ epoch 2a: priority group's x (gs floats) ==========
            const int fl = (int)(((unsigned)jmin * M) >> 22);
            const int j0 = fl * gs;
            float m = -1e30f;
            for (int t = lane; t < gs; t += 32) {
                const int j = j0 + t;
                if (j < n) m = fmaxf(m, __ldg(xr + j));
            }
            #pragma unroll
            for (int off = 16; off > 0; off >>= 1)
                m = fmaxf(m, __shfl_xor_sync(0xffffffffu, m, off));
            warp_loss = rank_loss_(sigmoidf_(m), 0.5f);
        } else {
            // ============ epoch 2b: x & y_neg, 16 loads in flight ============
            float mN = -1e30f, mW = -1e30f;
            if (lane < p) {
                const float xv = __ldg(xr + lane);
                mN = fmaxf(mN, xv);
                mW = fmaxf(mW, __ldg(ynr + lane) ? xv : -1e30f);
            }
            if (lane < ntail) {
                const int j = ts + lane;
                const float xv = __ldg(xr + j);
                mN = fmaxf(mN, xv);
                mW = fmaxf(mW, __ldg(ynr + j) ? xv : -1e30f);
            }
            for (int b0 = 0; b0 < nv; b0 += 256) {
                float4 xv[8];
                int4   nvv[8];
                #pragma unroll
                for (int k = 0; k < 8; k++) {
                    const int i = b0 + lane + k * 32;
                    const int j0 = p + 4 * i;
                    if (i < nv) {
                        xv[k]  = __ldg((const float4*)(xr  + j0));
                        nvv[k] = __ldg((const int4*)  (ynr + j0));
                    } else {
                        xv[k]  = make_float4(-1e30f, -1e30f, -1e30f, -1e30f);
                        nvv[k] = make_int4(0, 0, 0, 0);
                    }
                }
                #pragma unroll
                for (int k = 0; k < 8; k++) {
                    mN = fmaxf(mN, fmaxf(fmaxf(xv[k].x, xv[k].y),
                                         fmaxf(xv[k].z, xv[k].w)));
                    mW = fmaxf(mW, nvv[k].x ? xv[k].x : -1e30f);
                    mW = fmaxf(mW, nvv[k].y ? xv[k].y : -1e30f);
                    mW = fmaxf(mW, nvv[k].z ? xv[k].z : -1e30f);
                    mW = fmaxf(mW, nvv[k].w ? xv[k].w : -1e30f);
                }
            }
            #pragma unroll
            for (int off = 16; off > 0; off >>= 1) {
                mN = fmaxf(mN, __shfl_xor_sync(0xffffffffu, mN, off));
                mW = fmaxf(mW, __shfl_xor_sync(0xffffffffu, mW, off));
            }
            warp_loss = 0.5f * rank_loss_(0.5f, sigmoidf_(mN))
                      + 0.5f * rank_loss_(0.5f, sigmoidf_(mW));
        }
    } else if (row < B) {
        // ---------------- generic slow path (warp-per-row) ----------------
        const unsigned KNEG = enc_f(-1e30f);
        sG[wid][lane] = KNEG;
        __syncwarp();

        unsigned locNon = KNEG, locWrong = KNEG, locPres = 0u;
        for (int i = lane; i < n; i += 32) {
            const unsigned long long pk = g_pack[i];
            const int c         = (int)(pk & 0xffffffffull);
            const unsigned bits = (unsigned)(pk >> 32);
            const long long o = (long long)row * C + c;
            const float xv = __ldg(x + o);
            const unsigned key = enc_f(xv);
            locNon = max(locNon, key);
            if (__ldg(yneg + o) != 0) locWrong = max(locWrong, key);
            if (__ldg(y    + o) != 0) locPres |= bits;
            unsigned bb = bits;
            while (bb) {
                const int l = __ffs(bb) - 1;
                bb &= bb - 1u;
                atomicMax(&sG[wid][l], key);
            }
        }
        #pragma unroll
        for (int off = 16; off > 0; off >>= 1) {
            locNon   = max(locNon,   __shfl_xor_sync(0xffffffffu, locNon,   off));
            locWrong = max(locWrong, __shfl_xor_sync(0xffffffffu, locWrong, off));
            locPres |= __shfl_xor_sync(0xffffffffu, locPres, off);
        }
        __syncwarp();
        if (lane == 0) {
            if (locPres) {
                const int fl = __ffs(locPres) - 1;
                warp_loss = rank_loss_(sigmoidf_(dec_f(sG[wid][fl])), 0.5f);
            } else {
                warp_loss = 0.5f * rank_loss_(0.5f, sigmoidf_(dec_f(locNon)))
                          + 0.5f * rank_loss_(0.5f, sigmoidf_(dec_f(locWrong)));
            }
        }
    }

    if (lane == 0 && row < B) atomicAdd(&sSum, warp_loss);
    __syncthreads();
    if (threadIdx.x == 0) atomicAdd(out, sSum);
}

// ---------------------------------------------------------------------------
extern "C" void kernel_launch(void* const* d_in, const int* in_sizes, int n_in,
                              void* d_out, int out_size) {
    const float* x    = (const float*)d_in[0];
    const int*   y    = (const int*)d_in[1];
    const int*   yneg = (const int*)d_in[2];
    const void*  wl   = d_in[3];

    const int C = 9605;
    const int L = in_sizes[3] / C;            // 20
    const int B = in_sizes[0] / C;            // 4096

    float* out = (float*)d_out;

    init_kernel<<<1, 256>>>(out, out_size, (const unsigned int*)wl, 256);
    build_bits_kernel<<<(C + 255) / 256, 256>>>(wl, C, L);
    compact_kernel<<<(C + 255) / 256, 256>>>(C);
    row_loss_kernel<<<(B + 7) / 8, 256>>>(x, y, yneg, C, B, out);
}